// round 14
// baseline (speedup 1.0000x reference)
#include <cuda_runtime.h>
#include <cuda_fp16.h>
#include <cstdint>

// out = tanh( Xa @ W1'^T + T[b] ),  T = s @ W2^T,  s[b] = sum_a x[b,a,:]
// W1' = Wh - Wc/7, W2 = Wc/7. fp16 HMMA, fp32 accum.
// 128-row tiles (16 batch rows), 256-thread CTAs, 2 CTAs/SM.
// Per tile: [ bt0: GEMM+epilogue ; bt1: GEMM+epilogue ; convert(t+1)+LDG(t+2)
//            ; sync ; T-GEMM(t+1) ; sync ]
// acc is 16 regs (dies before convert) -> lower peak register pressure.
// Epilogue(t) reads T[p] written between iter(t-1)'s two barriers (ordered
// by its 2nd barrier). Streaming stores for out.

#define NTILES 4096  // 524288 / 128

#define X0 0
#define X1 16384
#define S0 32768
#define S1 34816
#define T0 36864
#define T1 40960
#define SMEM_SZ 45056

__device__ __forceinline__ uint32_t smem_u32(const void* p) {
    uint32_t a;
    asm("{ .reg .u64 t; cvta.to.shared.u64 t, %1; cvt.u32.u64 %0, t; }"
        : "=r"(a) : "l"(p));
    return a;
}

__device__ __forceinline__ uint32_t pack_h2(float a, float b) {
    __half2 t = __float22half2_rn(make_float2(a, b));
    return *reinterpret_cast<uint32_t*>(&t);
}

__device__ __forceinline__ void mma_fp16(float* c, const uint32_t* a,
                                         uint32_t b0, uint32_t b1) {
    asm volatile(
        "mma.sync.aligned.m16n8k16.row.col.f32.f16.f16.f32 "
        "{%0,%1,%2,%3}, {%4,%5,%6,%7}, {%8,%9}, {%0,%1,%2,%3};"
        : "+f"(c[0]), "+f"(c[1]), "+f"(c[2]), "+f"(c[3])
        : "r"(a[0]), "r"(a[1]), "r"(a[2]), "r"(a[3]), "r"(b0), "r"(b1));
}

__device__ __forceinline__ void ldsm4(uint32_t* r, uint32_t addr) {
    asm volatile(
        "ldmatrix.sync.aligned.m8n8.x4.shared.b16 {%0,%1,%2,%3}, [%4];"
        : "=r"(r[0]), "=r"(r[1]), "=r"(r[2]), "=r"(r[3]) : "r"(addr));
}

__device__ __forceinline__ float tanh_fast(float y) {
    float r;
    asm("tanh.approx.f32 %0, %1;" : "=f"(r) : "f"(y));
    return r;
}

__global__ void __launch_bounds__(256, 2)
comm_v13(const float* __restrict__ x, const float* __restrict__ Wh,
         const float* __restrict__ Wc, float* __restrict__ out) {
    __shared__ __align__(16) char sm[SMEM_SZ];
    const uint32_t sb = smem_u32(sm);

    const int tid = threadIdx.x;
    const int w = tid >> 5, lane = tid & 31;
    const int g = w >> 1, c = w & 1;
    const int q = lane >> 2, j = lane & 3;

    // ---- W1' B-frags in regs (32), permuted logical columns ----
    uint32_t bW[4][4][2];
#pragma unroll
    for (int ks = 0; ks < 4; ks++) {
#pragma unroll
        for (int nb = 0; nb < 4; nb++) {
            int n = (c << 5) + ((nb >> 1) << 4) + ((q >> 1) << 2) +
                    ((nb & 1) << 1) + (q & 1);
            int i00 = n * 64 + ks * 16 + j * 2;
            int i10 = i00 + 8;
            float w00 = Wh[i00] - Wc[i00] * (1.0f / 7.0f);
            float w01 = Wh[i00 + 1] - Wc[i00 + 1] * (1.0f / 7.0f);
            float w10 = Wh[i10] - Wc[i10] * (1.0f / 7.0f);
            float w11 = Wh[i10 + 1] - Wc[i10 + 1] * (1.0f / 7.0f);
            bW[ks][nb][0] = pack_h2(w00, w01);
            bW[ks][nb][1] = pack_h2(w10, w11);
        }
    }
    // ---- W2 B-frags for T-GEMM (8 regs): warp covers e-cols w*8..w*8+7 ----
    uint32_t bT[4][2];
#pragma unroll
    for (int ks = 0; ks < 4; ks++) {
        int n = (w << 3) + q;
        int i00 = n * 64 + ks * 16 + j * 2;
        int i10 = i00 + 8;
        bT[ks][0] = pack_h2(Wc[i00] * (1.0f / 7.0f), Wc[i00 + 1] * (1.0f / 7.0f));
        bT[ks][1] = pack_h2(Wc[i10] * (1.0f / 7.0f), Wc[i10 + 1] * (1.0f / 7.0f));
    }

    // ---- invariants ----
    const int arow = lane & 15, ahi = lane >> 4;
    uint32_t abase[2];
    int ar7[2];
#pragma unroll
    for (int bt = 0; bt < 2; bt++) {
        int r = g * 16 + bt * 64 + arow;
        abase[bt] = (uint32_t)(r << 7);
        ar7[bt] = r & 7;
    }
    const int bloc = 2 * w + (lane >> 4);  // staging batch row
    const int kc = lane & 15;              // staging float4 col
    const uint32_t sts_sw = (uint32_t)(((kc >> 1)) << 4) + ((kc & 1) << 3);
    const uint32_t s_ld_base = (uint32_t)(arow << 7);
    const int s_r7 = arow & 7;

    const int grid = gridDim.x;
    int t = blockIdx.x, p = 0;

    // ================= prologue =================
    float4 v[8];
    {
        const float4* xp =
            (const float4*)(x + (size_t)t * 8192 + bloc * 512 + kc * 4);
#pragma unroll
        for (int a = 0; a < 8; a++) v[a] = xp[a * 16];
        float sx = 0.f, sy = 0.f, sz = 0.f, sw = 0.f;
#pragma unroll
        for (int a = 0; a < 8; a++) {
            sx += v[a].x; sy += v[a].y; sz += v[a].z; sw += v[a].w;
            int r = bloc * 8 + a;
            uint32_t ro = (uint32_t)(r << 7) + (sts_sw ^ (uint32_t)((r & 7) << 4));
            *(uint2*)(sm + X0 + ro) =
                make_uint2(pack_h2(v[a].x, v[a].y), pack_h2(v[a].z, v[a].w));
        }
        uint32_t so = (uint32_t)(bloc << 7) +
                      (sts_sw ^ (uint32_t)((bloc & 7) << 4));
        *(uint2*)(sm + S0 + so) = make_uint2(pack_h2(sx, sy), pack_h2(sz, sw));
        if (t + grid < NTILES) {
            const float4* xn = (const float4*)(
                x + (size_t)(t + grid) * 8192 + bloc * 512 + kc * 4);
#pragma unroll
            for (int a = 0; a < 8; a++) v[a] = xn[a * 16];
        }
    }
    __syncthreads();
    // T-GEMM(t0) -> T[0]
    {
        float accT[4] = {0.f, 0.f, 0.f, 0.f};
#pragma unroll
        for (int ks = 0; ks < 4; ks++) {
            uint32_t a4[4];
            ldsm4(a4, sb + S0 + s_ld_base + ((((2 * ks + ahi) ^ s_r7)) << 4));
            mma_fp16(accT, a4, bT[ks][0], bT[ks][1]);
        }
        float* Tb = (float*)(sm + T0);
        int tc = (w << 3) + (j << 1);
        *(float2*)(Tb + q * 64 + tc) = make_float2(accT[0], accT[1]);
        *(float2*)(Tb + (q + 8) * 64 + tc) = make_float2(accT[2], accT[3]);
    }
    __syncthreads();  // order T(t0) before first epilogue

    // ============================ main loop ============================
    for (;;) {
        const uint32_t xbb = sb + (p ? X1 : X0);
        const float* Tb = (const float*)(sm + (p ? T1 : T0));

        // ---- per row-block: GEMM (4 ldsm4 + 16 MMA) then fused epilogue ----
#pragma unroll
        for (int bt = 0; bt < 2; bt++) {
            float acc[4][4] = {};
#pragma unroll
            for (int ks = 0; ks < 4; ks++) {
                uint32_t a[4];
                ldsm4(a, xbb + abase[bt] + ((((2 * ks + ahi) ^ ar7[bt])) << 4));
#pragma unroll
                for (int nb = 0; nb < 4; nb++)
                    mma_fp16(acc[nb], a, bW[ks][nb][0], bW[ks][nb][1]);
            }
            // epilogue: +T[p] (broadcast LDS.128), tanh, streaming STG.128
#pragma unroll
            for (int h = 0; h < 2; h++) {
                int bb = 2 * g + 8 * bt + h;
                int R = t * 128 + g * 16 + bt * 64 + h * 8 + q;
                const float* Trow = Tb + bb * 64 + (c << 5) + (j << 2);
                float* op = out + (size_t)R * 64 + (c << 5) + (j << 2);
#pragma unroll
                for (int m = 0; m < 2; m++) {
                    float4 tv = *(const float4*)(Trow + m * 16);
                    float4 o;
                    o.x = tanh_fast(acc[2 * m][2 * h] + tv.x);
                    o.y = tanh_fast(acc[2 * m][2 * h + 1] + tv.y);
                    o.z = tanh_fast(acc[2 * m + 1][2 * h] + tv.z);
                    o.w = tanh_fast(acc[2 * m + 1][2 * h + 1] + tv.w);
                    __stcs((float4*)(op + m * 16), o);
                }
            }
        }

        int tn = t + grid;
        bool more = (tn < NTILES);

        // ---- convert(t+1) -> X[1-p], s[1-p]; prefetch(t+2) ----
        if (more) {
            char* xb = sm + (p ? X0 : X1);
            char* sf = sm + (p ? S0 : S1);
            float sx = 0.f, sy = 0.f, sz = 0.f, sw = 0.f;
#pragma unroll
            for (int a = 0; a < 8; a++) {
                sx += v[a].x; sy += v[a].y; sz += v[a].z; sw += v[a].w;
                int r = bloc * 8 + a;
                uint32_t ro = (uint32_t)(r << 7) +
                              (sts_sw ^ (uint32_t)((r & 7) << 4));
                *(uint2*)(xb + ro) =
                    make_uint2(pack_h2(v[a].x, v[a].y), pack_h2(v[a].z, v[a].w));
            }
            uint32_t so = (uint32_t)(bloc << 7) +
                          (sts_sw ^ (uint32_t)((bloc & 7) << 4));
            *(uint2*)(sf + so) = make_uint2(pack_h2(sx, sy), pack_h2(sz, sw));
            if (tn + grid < NTILES) {
                const float4* xn = (const float4*)(
                    x + (size_t)(tn + grid) * 8192 + bloc * 512 + kc * 4);
#pragma unroll
                for (int a = 0; a < 8; a++) v[a] = xn[a * 16];
            }
        } else {
            break;
        }

        __syncthreads();  // X/s(t+1) ready

        // ---- T-GEMM(t+1) -> T[1-p] ----
        {
            float accT[4] = {0.f, 0.f, 0.f, 0.f};
            const uint32_t sbase = sb + (p ? S0 : S1) + s_ld_base;
#pragma unroll
            for (int ks = 0; ks < 4; ks++) {
                uint32_t a4[4];
                ldsm4(a4, sbase + ((((2 * ks + ahi) ^ s_r7)) << 4));
                mma_fp16(accT, a4, bT[ks][0], bT[ks][1]);
            }
            float* Tb2 = (float*)(sm + (p ? T0 : T1));
            int tc = (w << 3) + (j << 1);
            *(float2*)(Tb2 + q * 64 + tc) = make_float2(accT[0], accT[1]);
            *(float2*)(Tb2 + (q + 8) * 64 + tc) = make_float2(accT[2], accT[3]);
        }
        __syncthreads();  // T(t+1) ready before its epilogue next iteration

        t = tn;
        p ^= 1;
    }
}

extern "C" void kernel_launch(void* const* d_in, const int* in_sizes, int n_in,
                              void* d_out, int out_size) {
    const float* x  = (const float*)d_in[0];
    const float* Wh = (const float*)d_in[1];
    const float* Wc = (const float*)d_in[2];
    float* out = (float*)d_out;

    int dev = 0, sms = 148;
    cudaGetDevice(&dev);
    cudaDeviceGetAttribute(&sms, cudaDevAttrMultiProcessorCount, dev);

    comm_v13<<<2 * sms, 256>>>(x, Wh, Wc, out);
}

// round 15
// speedup vs baseline: 1.0401x; 1.0401x over previous
#include <cuda_runtime.h>
#include <cuda_fp16.h>
#include <cstdint>

// out = tanh( Xa @ W1'^T + T[b] ),  T = s @ W2^T,  s[b] = sum_a x[b,a,:]
// W1' = Wh - Wc/7, W2 = Wc/7. fp16 HMMA, fp32 accum.
// v12 structure (best known) + streaming loads (__ldcs) for x and paired
// ldsm4 issue in the main GEMM.
// 128-row tiles (16 batch rows), 256-thread CTAs, 2 CTAs/SM, ONE barrier
// per tile: [ main GEMM(t) ; convert(t+1)+prefetch(t+2) ; sync ;
//             T-GEMM(t+1) ; epilogue(t) with T[p] ]

#define NTILES 4096  // 524288 / 128

#define X0 0
#define X1 16384
#define S0 32768
#define S1 34816
#define T0 36864
#define T1 40960
#define SMEM_SZ 45056

__device__ __forceinline__ uint32_t smem_u32(const void* p) {
    uint32_t a;
    asm("{ .reg .u64 t; cvta.to.shared.u64 t, %1; cvt.u32.u64 %0, t; }"
        : "=r"(a) : "l"(p));
    return a;
}

__device__ __forceinline__ uint32_t pack_h2(float a, float b) {
    __half2 t = __float22half2_rn(make_float2(a, b));
    return *reinterpret_cast<uint32_t*>(&t);
}

__device__ __forceinline__ void mma_fp16(float* c, const uint32_t* a,
                                         uint32_t b0, uint32_t b1) {
    asm volatile(
        "mma.sync.aligned.m16n8k16.row.col.f32.f16.f16.f32 "
        "{%0,%1,%2,%3}, {%4,%5,%6,%7}, {%8,%9}, {%0,%1,%2,%3};"
        : "+f"(c[0]), "+f"(c[1]), "+f"(c[2]), "+f"(c[3])
        : "r"(a[0]), "r"(a[1]), "r"(a[2]), "r"(a[3]), "r"(b0), "r"(b1));
}

__device__ __forceinline__ void ldsm4(uint32_t* r, uint32_t addr) {
    asm volatile(
        "ldmatrix.sync.aligned.m8n8.x4.shared.b16 {%0,%1,%2,%3}, [%4];"
        : "=r"(r[0]), "=r"(r[1]), "=r"(r[2]), "=r"(r[3]) : "r"(addr));
}

__device__ __forceinline__ float tanh_fast(float y) {
    float r;
    asm("tanh.approx.f32 %0, %1;" : "=f"(r) : "f"(y));
    return r;
}

// Streaming (evict-first) float4 load: x is read exactly once.
__device__ __forceinline__ float4 ldcs4(const float4* p) {
    float4 v;
    asm volatile("ld.global.cs.v4.f32 {%0,%1,%2,%3}, [%4];"
                 : "=f"(v.x), "=f"(v.y), "=f"(v.z), "=f"(v.w) : "l"(p));
    return v;
}

__global__ void __launch_bounds__(256, 2)
comm_v14(const float* __restrict__ x, const float* __restrict__ Wh,
         const float* __restrict__ Wc, float* __restrict__ out) {
    __shared__ __align__(16) char sm[SMEM_SZ];
    const uint32_t sb = smem_u32(sm);

    const int tid = threadIdx.x;
    const int w = tid >> 5, lane = tid & 31;
    const int g = w >> 1, c = w & 1;
    const int q = lane >> 2, j = lane & 3;

    // ---- W1' B-frags in regs (32), permuted logical columns ----
    uint32_t bW[4][4][2];
#pragma unroll
    for (int ks = 0; ks < 4; ks++) {
#pragma unroll
        for (int nb = 0; nb < 4; nb++) {
            int n = (c << 5) + ((nb >> 1) << 4) + ((q >> 1) << 2) +
                    ((nb & 1) << 1) + (q & 1);
            int i00 = n * 64 + ks * 16 + j * 2;
            int i10 = i00 + 8;
            float w00 = Wh[i00] - Wc[i00] * (1.0f / 7.0f);
            float w01 = Wh[i00 + 1] - Wc[i00 + 1] * (1.0f / 7.0f);
            float w10 = Wh[i10] - Wc[i10] * (1.0f / 7.0f);
            float w11 = Wh[i10 + 1] - Wc[i10 + 1] * (1.0f / 7.0f);
            bW[ks][nb][0] = pack_h2(w00, w01);
            bW[ks][nb][1] = pack_h2(w10, w11);
        }
    }
    // ---- W2 B-frags for T-GEMM (8 regs): warp covers e-cols w*8..w*8+7 ----
    uint32_t bT[4][2];
#pragma unroll
    for (int ks = 0; ks < 4; ks++) {
        int n = (w << 3) + q;
        int i00 = n * 64 + ks * 16 + j * 2;
        int i10 = i00 + 8;
        bT[ks][0] = pack_h2(Wc[i00] * (1.0f / 7.0f), Wc[i00 + 1] * (1.0f / 7.0f));
        bT[ks][1] = pack_h2(Wc[i10] * (1.0f / 7.0f), Wc[i10 + 1] * (1.0f / 7.0f));
    }

    // ---- invariants ----
    const int arow = lane & 15, ahi = lane >> 4;
    uint32_t abase[2];
    int ar7[2];
#pragma unroll
    for (int bt = 0; bt < 2; bt++) {
        int r = g * 16 + bt * 64 + arow;
        abase[bt] = (uint32_t)(r << 7);
        ar7[bt] = r & 7;
    }
    const int bloc = 2 * w + (lane >> 4);  // staging batch row
    const int kc = lane & 15;              // staging float4 col
    const uint32_t sts_sw = (uint32_t)(((kc >> 1)) << 4) + ((kc & 1) << 3);
    const uint32_t s_ld_base = (uint32_t)(arow << 7);
    const int s_r7 = arow & 7;

    const int grid = gridDim.x;
    int t = blockIdx.x, p = 0;

    // ================= prologue =================
    float4 v[8];
    {
        const float4* xp =
            (const float4*)(x + (size_t)t * 8192 + bloc * 512 + kc * 4);
#pragma unroll
        for (int a = 0; a < 8; a++) v[a] = ldcs4(xp + a * 16);
        float sx = 0.f, sy = 0.f, sz = 0.f, sw = 0.f;
#pragma unroll
        for (int a = 0; a < 8; a++) {
            sx += v[a].x; sy += v[a].y; sz += v[a].z; sw += v[a].w;
            int r = bloc * 8 + a;
            uint32_t ro = (uint32_t)(r << 7) + (sts_sw ^ (uint32_t)((r & 7) << 4));
            *(uint2*)(sm + X0 + ro) =
                make_uint2(pack_h2(v[a].x, v[a].y), pack_h2(v[a].z, v[a].w));
        }
        uint32_t so = (uint32_t)(bloc << 7) +
                      (sts_sw ^ (uint32_t)((bloc & 7) << 4));
        *(uint2*)(sm + S0 + so) = make_uint2(pack_h2(sx, sy), pack_h2(sz, sw));
        if (t + grid < NTILES) {
            const float4* xn = (const float4*)(
                x + (size_t)(t + grid) * 8192 + bloc * 512 + kc * 4);
#pragma unroll
            for (int a = 0; a < 8; a++) v[a] = ldcs4(xn + a * 16);
        }
    }
    __syncthreads();
    // T-GEMM(t0) -> T[0]
    {
        float accT[4] = {0.f, 0.f, 0.f, 0.f};
#pragma unroll
        for (int ks = 0; ks < 4; ks++) {
            uint32_t a4[4];
            ldsm4(a4, sb + S0 + s_ld_base + ((((2 * ks + ahi) ^ s_r7)) << 4));
            mma_fp16(accT, a4, bT[ks][0], bT[ks][1]);
        }
        float* Tb = (float*)(sm + T0);
        int tc = (w << 3) + (j << 1);
        *(float2*)(Tb + q * 64 + tc) = make_float2(accT[0], accT[1]);
        *(float2*)(Tb + (q + 8) * 64 + tc) = make_float2(accT[2], accT[3]);
    }

    // ============================ main loop ============================
    for (;;) {
        // ---- main GEMM(t): 8 ldsm4 (paired) + 32 MMA from X[p] ----
        float acc[2][4][4] = {};
        const uint32_t xbb = sb + (p ? X1 : X0);
#pragma unroll
        for (int ks = 0; ks < 4; ks++) {
            uint32_t a0[4], a1[4];
            ldsm4(a0, xbb + abase[0] + ((((2 * ks + ahi) ^ ar7[0])) << 4));
            ldsm4(a1, xbb + abase[1] + ((((2 * ks + ahi) ^ ar7[1])) << 4));
#pragma unroll
            for (int nb = 0; nb < 4; nb++)
                mma_fp16(acc[0][nb], a0, bW[ks][nb][0], bW[ks][nb][1]);
#pragma unroll
            for (int nb = 0; nb < 4; nb++)
                mma_fp16(acc[1][nb], a1, bW[ks][nb][0], bW[ks][nb][1]);
        }

        int tn = t + grid;
        bool more = (tn < NTILES);

        // ---- convert(t+1) -> X[1-p], s[1-p]; prefetch(t+2) ----
        if (more) {
            char* xb = sm + (p ? X0 : X1);
            char* sf = sm + (p ? S0 : S1);
            float sx = 0.f, sy = 0.f, sz = 0.f, sw = 0.f;
#pragma unroll
            for (int a = 0; a < 8; a++) {
                sx += v[a].x; sy += v[a].y; sz += v[a].z; sw += v[a].w;
                int r = bloc * 8 + a;
                uint32_t ro = (uint32_t)(r << 7) +
                              (sts_sw ^ (uint32_t)((r & 7) << 4));
                *(uint2*)(xb + ro) =
                    make_uint2(pack_h2(v[a].x, v[a].y), pack_h2(v[a].z, v[a].w));
            }
            uint32_t so = (uint32_t)(bloc << 7) +
                          (sts_sw ^ (uint32_t)((bloc & 7) << 4));
            *(uint2*)(sf + so) = make_uint2(pack_h2(sx, sy), pack_h2(sz, sw));
            if (tn + grid < NTILES) {
                const float4* xn = (const float4*)(
                    x + (size_t)(tn + grid) * 8192 + bloc * 512 + kc * 4);
#pragma unroll
                for (int a = 0; a < 8; a++) v[a] = ldcs4(xn + a * 16);
            }
        }

        __syncthreads();  // the ONLY barrier per tile

        // ---- T-GEMM(t+1) -> T[1-p] ----
        if (more) {
            float accT[4] = {0.f, 0.f, 0.f, 0.f};
            const uint32_t sbase = sb + (p ? S0 : S1) + s_ld_base;
#pragma unroll
            for (int ks = 0; ks < 4; ks++) {
                uint32_t a4[4];
                ldsm4(a4, sbase + ((((2 * ks + ahi) ^ s_r7)) << 4));
                mma_fp16(accT, a4, bT[ks][0], bT[ks][1]);
            }
            float* Tb = (float*)(sm + (p ? T0 : T1));
            int tc = (w << 3) + (j << 1);
            *(float2*)(Tb + q * 64 + tc) = make_float2(accT[0], accT[1]);
            *(float2*)(Tb + (q + 8) * 64 + tc) = make_float2(accT[2], accT[3]);
        }

        // ---- epilogue(t): +T[p] (broadcast LDS.128), tanh, streaming STG ----
        {
            const float* Tb = (const float*)(sm + (p ? T1 : T0));
#pragma unroll
            for (int bt = 0; bt < 2; bt++) {
#pragma unroll
                for (int h = 0; h < 2; h++) {
                    int bb = 2 * g + 8 * bt + h;
                    int R = t * 128 + g * 16 + bt * 64 + h * 8 + q;
                    const float* Trow = Tb + bb * 64 + (c << 5) + (j << 2);
                    float* op = out + (size_t)R * 64 + (c << 5) + (j << 2);
#pragma unroll
                    for (int m = 0; m < 2; m++) {
                        float4 tv = *(const float4*)(Trow + m * 16);
                        float4 o;
                        o.x = tanh_fast(acc[bt][2 * m][2 * h] + tv.x);
                        o.y = tanh_fast(acc[bt][2 * m][2 * h + 1] + tv.y);
                        o.z = tanh_fast(acc[bt][2 * m + 1][2 * h] + tv.z);
                        o.w = tanh_fast(acc[bt][2 * m + 1][2 * h + 1] + tv.w);
                        __stcs((float4*)(op + m * 16), o);
                    }
                }
            }
        }

        if (!more) break;
        t = tn;
        p ^= 1;
    }
}

extern "C" void kernel_launch(void* const* d_in, const int* in_sizes, int n_in,
                              void* d_out, int out_size) {
    const float* x  = (const float*)d_in[0];
    const float* Wh = (const float*)d_in[1];
    const float* Wc = (const float*)d_in[2];
    float* out = (float*)d_out;

    int dev = 0, sms = 148;
    cudaGetDevice(&dev);
    cudaDeviceGetAttribute(&sms, cudaDevAttrMultiProcessorCount, dev);

    comm_v14<<<2 * sms, 256>>>(x, Wh, Wc, out);
}